// round 2
// baseline (speedup 1.0000x reference)
#include <cuda_runtime.h>
#include <cuda_bf16.h>

// Problem constants (HawkesIntensityFunction: B=2, N=4096, D=256)
#define BATCH 2
#define NLEN  4096
#define DM    256
#define LOG2E 1.4426950408889634f

__device__ __forceinline__ float ex2_approx(float x) {
    float r; asm("ex2.approx.f32 %0, %1;" : "=f"(r) : "f"(x)); return r;
}
__device__ __forceinline__ float sqrt_approx(float x) {
    float r; asm("sqrt.approx.f32 %0, %1;" : "=f"(r) : "f"(x)); return r;
}

// One warp handles TWO rows: r and NLEN-1-r  -> exactly (NLEN-1) pairs per warp
// (perfect static load balance over the strict upper triangle).
// Since the triu mask is applied BEFORE exp in the reference, entries j<=i
// contribute exp(0)*exp(0) = 1 each, i.e. a closed-form alpha*(i+1).
// excitation[i] = alpha*(i+1) + alpha * sum_{j>i} exp(-beta*(t_i-t_j) - gamma*dist_ij)
// intensity[i]  = mu + exp(dot(z_i,w)+b) + excitation[i]
__global__ __launch_bounds__(256)
void hawkes_kernel(const float* __restrict__ z,
                   const float* __restrict__ t,
                   const float* __restrict__ loc,
                   const float* __restrict__ w,
                   const float* __restrict__ bias,
                   const float* __restrict__ mu,
                   const float* __restrict__ alpha,
                   const float* __restrict__ beta,
                   const float* __restrict__ gamma,
                   float* __restrict__ out)
{
    const int lane   = threadIdx.x & 31;
    const int warp   = threadIdx.x >> 5;
    const int gwarp  = blockIdx.x * 8 + warp;          // 4096 warps total
    const int b      = gwarp / (NLEN / 2);             // batch
    const int r      = gwarp % (NLEN / 2);             // 0..2047

    // scalars (uniform loads, L1/L2 cached)
    const float muv   = __ldg(mu);
    const float av    = __ldg(alpha);
    const float bv    = __ldg(bias);
    const float nb2   = -__ldg(beta)  * LOG2E;         // fold exp -> ex2
    const float ng2   = -__ldg(gamma) * LOG2E;

    const float*  tb = t   + (size_t)b * NLEN;
    const float2* lb = (const float2*)(loc + (size_t)b * NLEN * 2);
    const float4* wr = (const float4*)w;

    // load w slice once per warp (reused for both rows)
    const float4 w0 = __ldg(wr + lane * 2 + 0);
    const float4 w1 = __ldg(wr + lane * 2 + 1);

    int rows[2];
    rows[0] = r;
    rows[1] = NLEN - 1 - r;

    #pragma unroll
    for (int rr = 0; rr < 2; rr++) {
        const int i = rows[rr];

        // ---- base intensity dot product: 8 elems per lane ----
        const float4* zr = (const float4*)(z + ((size_t)b * NLEN + i) * DM);
        const float4 a0 = __ldg(zr + lane * 2 + 0);
        const float4 a1 = __ldg(zr + lane * 2 + 1);
        float dotp;
        dotp = a0.x * w0.x;
        dotp = fmaf(a0.y, w0.y, dotp);
        dotp = fmaf(a0.z, w0.z, dotp);
        dotp = fmaf(a0.w, w0.w, dotp);
        dotp = fmaf(a1.x, w1.x, dotp);
        dotp = fmaf(a1.y, w1.y, dotp);
        dotp = fmaf(a1.z, w1.z, dotp);
        dotp = fmaf(a1.w, w1.w, dotp);

        // ---- excitation over j > i ----
        const float  ti = __ldg(tb + i);
        const float2 li = __ldg(lb + i);
        float acc0 = 0.0f, acc1 = 0.0f;   // dual accumulators: shorten FADD chain after MUFU

        int j = i + 1 + lane;
        #pragma unroll 8
        for (; j + 32 < NLEN; j += 64) {
            // iteration A
            {
                const float  tj = __ldg(tb + j);
                const float2 lj = __ldg(lb + j);
                const float dt = ti - tj;
                const float dx = li.x - lj.x;
                const float dy = li.y - lj.y;
                const float sq = fmaf(dx, dx, dy * dy);
                acc0 += ex2_approx(fmaf(ng2, sqrt_approx(sq), nb2 * dt));
            }
            // iteration B (independent)
            {
                const int    j2 = j + 32;
                const float  tj = __ldg(tb + j2);
                const float2 lj = __ldg(lb + j2);
                const float dt = ti - tj;
                const float dx = li.x - lj.x;
                const float dy = li.y - lj.y;
                const float sq = fmaf(dx, dx, dy * dy);
                acc1 += ex2_approx(fmaf(ng2, sqrt_approx(sq), nb2 * dt));
            }
        }
        for (; j < NLEN; j += 32) {
            const float  tj = __ldg(tb + j);
            const float2 lj = __ldg(lb + j);
            const float dt = ti - tj;
            const float dx = li.x - lj.x;
            const float dy = li.y - lj.y;
            const float sq = fmaf(dx, dx, dy * dy);
            acc0 += ex2_approx(fmaf(ng2, sqrt_approx(sq), nb2 * dt));
        }
        float acc = acc0 + acc1;

        // ---- warp reduce both sums ----
        #pragma unroll
        for (int off = 16; off > 0; off >>= 1) {
            acc  += __shfl_xor_sync(0xffffffffu, acc,  off);
            dotp += __shfl_xor_sync(0xffffffffu, dotp, off);
        }

        if (lane == 0) {
            const float base = ex2_approx((dotp + bv) * LOG2E);
            out[(size_t)b * NLEN + i] =
                muv + base + av * ((float)(i + 1) + acc);
        }
    }
}

extern "C" void kernel_launch(void* const* d_in, const int* in_sizes, int n_in,
                              void* d_out, int out_size)
{
    const float* z     = (const float*)d_in[0];
    const float* t     = (const float*)d_in[1];
    const float* loc   = (const float*)d_in[2];
    const float* w     = (const float*)d_in[3];
    const float* bias  = (const float*)d_in[4];
    const float* mu    = (const float*)d_in[5];
    const float* alpha = (const float*)d_in[6];
    const float* beta  = (const float*)d_in[7];
    const float* gamma = (const float*)d_in[8];
    float* out = (float*)d_out;

    // 4096 warps, 8 warps (256 threads) per block -> 512 blocks
    hawkes_kernel<<<512, 256>>>(z, t, loc, w, bias, mu, alpha, beta, gamma, out);
}